// round 1
// baseline (speedup 1.0000x reference)
#include <cuda_runtime.h>
#include <math.h>

// ---- problem constants ----
#define BB    16
#define HH    128
#define WWID  128
#define CC    192
#define WS    8
#define SHIFTV 4
#define HEADS 6
#define NN    64          // WS*WS
#define HD    32          // CC/HEADS
#define TT    (BB*HH*WWID)   // 262144 tokens
#define NWIN  256            // windows per image (16x16)
#define BWIN  (BB*NWIN)      // 4096 windows total
#define C3    (3*CC)         // 576
#define C4    (4*CC)         // 768
#define SCALE 0.17677669529663687f   // 1/sqrt(32)

// ---- scratch (device globals; no allocation allowed) ----
__device__ float g_xw  [(size_t)TT*CC];   // LN1 windowed input; reused for LN2 output
__device__ float g_qkv [(size_t)TT*C3];
__device__ float g_attn[(size_t)TT*CC];
__device__ float g_h   [(size_t)TT*CC];   // shortcut + attn branch (original order)
__device__ float g_m1  [(size_t)TT*C4];   // gelu(fc1) output

// Map windowed token index -> original token index (same map for gather & scatter:
// shifted coord (rr,cc) corresponds to original ((rr+SHIFT)&127, (cc+SHIFT)&127)).
__device__ __forceinline__ int win_to_orig(int tw) {
    int n  = tw & 63;
    int bw = tw >> 6;
    int ww = bw & 15;
    int wh = (bw >> 4) & 15;
    int b  = bw >> 8;
    int ri = n >> 3, ci = n & 7;
    int r = (wh * 8 + ri + SHIFTV) & 127;
    int c = (ww * 8 + ci + SHIFTV) & 127;
    return (b << 14) + (r << 7) + c;
}

// ---------------- LayerNorm (warp per token, C=192 = 6 per lane) ----------------
template<int GATHER>
__global__ void ln_kernel(const float* __restrict__ in, const float* __restrict__ gg,
                          const float* __restrict__ bb, float* __restrict__ out) {
    int warp = blockIdx.x * (blockDim.x >> 5) + (threadIdx.x >> 5);
    int lane = threadIdx.x & 31;
    int src = GATHER ? win_to_orig(warp) : warp;
    const float* ip = in + (size_t)src * CC;
    float v[6];
    float s = 0.f, s2 = 0.f;
#pragma unroll
    for (int k = 0; k < 6; k++) {
        v[k] = ip[lane + 32 * k];
        s += v[k];
        s2 += v[k] * v[k];
    }
#pragma unroll
    for (int o = 16; o; o >>= 1) {
        s  += __shfl_xor_sync(0xffffffffu, s,  o);
        s2 += __shfl_xor_sync(0xffffffffu, s2, o);
    }
    float mean = s * (1.f / CC);
    float var  = s2 * (1.f / CC) - mean * mean;
    float rstd = rsqrtf(var + 1e-5f);
    float* op = out + (size_t)warp * CC;
#pragma unroll
    for (int k = 0; k < 6; k++) {
        int c = lane + 32 * k;
        op[c] = (v[k] - mean) * rstd * gg[c] + bb[c];
    }
}

// ---------------- GEMM: out[M,N] = A[M,K] @ W[N,K]^T (+ epilogue) ----------------
// BM=128, BN=64, BK=16; 256 threads; each thread 8x4 outputs.
// EPI 0: +bias                          (qkv)
// EPI 1: +bias, scatter to orig, +x     (proj + residual)
// EPI 2: +bias, exact gelu              (fc1)
// EPI 3: +bias, +aux (h), plain store   (fc2 + residual)
#define GBM 128
#define GBN 64
#define GBK 16

template<int EPI>
__global__ __launch_bounds__(256)
void gemm_kernel(const float* __restrict__ A, const float* __restrict__ W,
                 const float* __restrict__ bias, float* __restrict__ out,
                 const float* __restrict__ aux, int N, int K) {
    __shared__ float As[GBK][GBM];
    __shared__ float Bs[GBK][GBN];
    int tid = threadIdx.x;
    int m0 = blockIdx.y * GBM;
    int n0 = blockIdx.x * GBN;
    int tx = tid & 15;        // 16 col-groups of 4
    int ty = tid >> 4;        // 16 row-groups of 8

    float acc[8][4];
#pragma unroll
    for (int i = 0; i < 8; i++)
#pragma unroll
        for (int j = 0; j < 4; j++) acc[i][j] = 0.f;

    int arow = tid >> 2;           // 0..63
    int ak   = (tid & 3) * 4;      // 0,4,8,12
    const float* Ap0 = A + (size_t)(m0 + arow) * K + ak;
    const float* Ap1 = A + (size_t)(m0 + arow + 64) * K + ak;
    const float* Wp  = W + (size_t)(n0 + arow) * K + ak;

    for (int k0 = 0; k0 < K; k0 += GBK) {
        float4 a0 = *(const float4*)(Ap0 + k0);
        float4 a1 = *(const float4*)(Ap1 + k0);
        float4 b0 = *(const float4*)(Wp  + k0);
        __syncthreads();
        As[ak + 0][arow]      = a0.x;  As[ak + 1][arow]      = a0.y;
        As[ak + 2][arow]      = a0.z;  As[ak + 3][arow]      = a0.w;
        As[ak + 0][arow + 64] = a1.x;  As[ak + 1][arow + 64] = a1.y;
        As[ak + 2][arow + 64] = a1.z;  As[ak + 3][arow + 64] = a1.w;
        Bs[ak + 0][arow] = b0.x;  Bs[ak + 1][arow] = b0.y;
        Bs[ak + 2][arow] = b0.z;  Bs[ak + 3][arow] = b0.w;
        __syncthreads();
#pragma unroll
        for (int k = 0; k < GBK; k++) {
            float4 av0 = *(const float4*)&As[k][ty * 8];
            float4 av1 = *(const float4*)&As[k][ty * 8 + 4];
            float4 bv  = *(const float4*)&Bs[k][tx * 4];
            float ar[8] = {av0.x, av0.y, av0.z, av0.w, av1.x, av1.y, av1.z, av1.w};
            float br[4] = {bv.x, bv.y, bv.z, bv.w};
#pragma unroll
            for (int i = 0; i < 8; i++)
#pragma unroll
                for (int j = 0; j < 4; j++) acc[i][j] += ar[i] * br[j];
        }
    }

#pragma unroll
    for (int i = 0; i < 8; i++) {
        int r = m0 + ty * 8 + i;
        size_t obase;
        if (EPI == 1) obase = (size_t)win_to_orig(r) * CC;
        else          obase = (size_t)r * N;
#pragma unroll
        for (int j = 0; j < 4; j++) {
            int c = n0 + tx * 4 + j;
            float v = acc[i][j] + bias[c];
            if (EPI == 1) {
                v += aux[obase + c];           // + shortcut x
                out[obase + c] = v;
            } else if (EPI == 2) {
                v = 0.5f * v * (1.f + erff(v * 0.70710678118654752f));
                out[obase + c] = v;
            } else if (EPI == 3) {
                out[obase + c] = v + aux[obase + c];   // + h residual
            } else {
                out[obase + c] = v;
            }
        }
    }
}

// ---------------- Windowed attention: block per (window, head), 64 threads ----------------
__global__ __launch_bounds__(64)
void attn_kernel(const float* __restrict__ qkv, const float* __restrict__ rpb,
                 float* __restrict__ outp) {
    int bidx = blockIdx.x;
    int head = bidx % HEADS;
    int w    = bidx / HEADS;
    int widx = w & 255;
    int wh = widx >> 4, ww = widx & 15;
    int i = threadIdx.x;                 // row 0..63

    __shared__ float ks[NN][HD];
    __shared__ float vs[NN][HD];

    size_t rowbase = ((size_t)w * NN + i) * C3;
    float qr[HD];
#pragma unroll
    for (int d = 0; d < HD; d += 4) {
        float4 qv = *(const float4*)(qkv + rowbase + head * HD + d);
        qr[d + 0] = qv.x * SCALE; qr[d + 1] = qv.y * SCALE;
        qr[d + 2] = qv.z * SCALE; qr[d + 3] = qv.w * SCALE;
    }
#pragma unroll
    for (int d = 0; d < HD; d += 4) {
        float4 kv = *(const float4*)(qkv + rowbase + CC + head * HD + d);
        ks[i][d + 0] = kv.x; ks[i][d + 1] = kv.y; ks[i][d + 2] = kv.z; ks[i][d + 3] = kv.w;
        float4 vv = *(const float4*)(qkv + rowbase + 2 * CC + head * HD + d);
        vs[i][d + 0] = vv.x; vs[i][d + 1] = vv.y; vs[i][d + 2] = vv.z; vs[i][d + 3] = vv.w;
    }
    __syncthreads();

    int ri = i >> 3, ci = i & 7;
    int gr = wh * 8 + ri, gc = ww * 8 + ci;
    int rh = (gr < HH - WS) ? 0 : ((gr < HH - SHIFTV) ? 1 : 2);
    int rw = (gc < WWID - WS) ? 0 : ((gc < WWID - SHIFTV) ? 1 : 2);
    int cnt_i = rh * 3 + rw;

    float s[NN];
#pragma unroll
    for (int j = 0; j < NN; j++) {
        float acc = 0.f;
#pragma unroll
        for (int d = 0; d < HD; d++) acc += qr[d] * ks[j][d];
        int rj = j >> 3, cj = j & 7;
        int idx = (ri - rj + 7) * 15 + (ci - cj + 7);
        acc += rpb[idx * HEADS + head];
        int gjr = wh * 8 + rj, gjc = ww * 8 + cj;
        int rhj = (gjr < HH - WS) ? 0 : ((gjr < HH - SHIFTV) ? 1 : 2);
        int rwj = (gjc < WWID - WS) ? 0 : ((gjc < WWID - SHIFTV) ? 1 : 2);
        if (rhj * 3 + rwj != cnt_i) acc += -100.0f;
        s[j] = acc;
    }
    float mx = -1e30f;
#pragma unroll
    for (int j = 0; j < NN; j++) mx = fmaxf(mx, s[j]);
    float sum = 0.f;
#pragma unroll
    for (int j = 0; j < NN; j++) { s[j] = __expf(s[j] - mx); sum += s[j]; }
    float inv = 1.f / sum;

    size_t obase = ((size_t)w * NN + i) * CC + head * HD;
#pragma unroll
    for (int d = 0; d < HD; d++) {
        float o = 0.f;
#pragma unroll
        for (int j = 0; j < NN; j++) o += s[j] * vs[j][d];
        outp[obase + d] = o * inv;
    }
}

// ---------------- host ----------------
extern "C" void kernel_launch(void* const* d_in, const int* in_sizes, int n_in,
                              void* d_out, int out_size) {
    const float* x     = (const float*)d_in[0];
    const float* n1g   = (const float*)d_in[1];
    const float* n1b   = (const float*)d_in[2];
    const float* qkvw  = (const float*)d_in[3];
    const float* qkvb  = (const float*)d_in[4];
    const float* projw = (const float*)d_in[5];
    const float* projb = (const float*)d_in[6];
    const float* rpb   = (const float*)d_in[7];
    const float* n2g   = (const float*)d_in[8];
    const float* n2b   = (const float*)d_in[9];
    const float* fc1w  = (const float*)d_in[10];
    const float* fc1b  = (const float*)d_in[11];
    const float* fc2w  = (const float*)d_in[12];
    const float* fc2b  = (const float*)d_in[13];
    float* out = (float*)d_out;

    float *xw, *qkv, *attn, *h, *m1;
    cudaGetSymbolAddress((void**)&xw,   g_xw);
    cudaGetSymbolAddress((void**)&qkv,  g_qkv);
    cudaGetSymbolAddress((void**)&attn, g_attn);
    cudaGetSymbolAddress((void**)&h,    g_h);
    cudaGetSymbolAddress((void**)&m1,   g_m1);

    // 1. LN1 + shift + window partition
    ln_kernel<1><<<TT / 8, 256>>>(x, n1g, n1b, xw);
    // 2. QKV GEMM: [T,192] x [576,192]^T
    gemm_kernel<0><<<dim3(C3 / GBN, TT / GBM), 256>>>(xw, qkvw, qkvb, qkv, nullptr, C3, CC);
    // 3. Attention per (window, head)
    attn_kernel<<<BWIN * HEADS, 64>>>(qkv, rpb, attn);
    // 4. Proj GEMM + window reverse + unshift + residual(x)
    gemm_kernel<1><<<dim3(CC / GBN, TT / GBM), 256>>>(attn, projw, projb, h, x, CC, CC);
    // 5. LN2 (reuse xw buffer)
    ln_kernel<0><<<TT / 8, 256>>>(h, n2g, n2b, xw);
    // 6. FC1 GEMM + GELU
    gemm_kernel<2><<<dim3(C4 / GBN, TT / GBM), 256>>>(xw, fc1w, fc1b, m1, nullptr, C4, CC);
    // 7. FC2 GEMM + residual(h) -> final output
    gemm_kernel<3><<<dim3(CC / GBN, TT / GBM), 256>>>(m1, fc2w, fc2b, out, h, CC, C4);
}

// round 3
// speedup vs baseline: 2.3329x; 2.3329x over previous
#include <cuda_runtime.h>
#include <cstdint>
#include <math.h>

// ---- problem constants ----
#define BB    16
#define HH    128
#define WWID  128
#define CC    192
#define WS    8
#define SHIFTV 4
#define HEADS 6
#define NN    64
#define HD    32
#define TT    (BB*HH*WWID)   // 262144
#define NWIN  256
#define BWIN  (BB*NWIN)      // 4096
#define C3    (3*CC)         // 576
#define C4    (4*CC)         // 768
#define SCALE 0.17677669529663687f

// ---- scratch ----
__device__ float g_xw  [(size_t)TT*CC];
__device__ float g_qkv [(size_t)TT*C3];
__device__ float g_attn[(size_t)TT*CC];
__device__ float g_h   [(size_t)TT*CC];
__device__ float g_m1  [(size_t)TT*C4];

__device__ __forceinline__ uint32_t f2tf32(float f) {
    uint32_t u;
    asm("cvt.rna.tf32.f32 %0, %1;" : "=r"(u) : "f"(f));
    return u;
}

__device__ __forceinline__ void mma_tf32(float c[4],
    uint32_t a0, uint32_t a1, uint32_t a2, uint32_t a3, uint32_t b0, uint32_t b1) {
    asm volatile("mma.sync.aligned.m16n8k8.row.col.f32.tf32.tf32.f32 "
        "{%0,%1,%2,%3}, {%4,%5,%6,%7}, {%8,%9}, {%0,%1,%2,%3};"
        : "+f"(c[0]), "+f"(c[1]), "+f"(c[2]), "+f"(c[3])
        : "r"(a0), "r"(a1), "r"(a2), "r"(a3), "r"(b0), "r"(b1));
}

__device__ __forceinline__ int win_to_orig(int tw) {
    int n  = tw & 63;
    int bw = tw >> 6;
    int ww = bw & 15;
    int wh = (bw >> 4) & 15;
    int b  = bw >> 8;
    int ri = n >> 3, ci = n & 7;
    int r = (wh * 8 + ri + SHIFTV) & 127;
    int c = (ww * 8 + ci + SHIFTV) & 127;
    return (b << 14) + (r << 7) + c;
}

// ================= LayerNorm =================
template<int GATHER>
__global__ void ln_kernel(const float* __restrict__ in, const float* __restrict__ gg,
                          const float* __restrict__ bb, float* __restrict__ out) {
    int warp = blockIdx.x * (blockDim.x >> 5) + (threadIdx.x >> 5);
    int lane = threadIdx.x & 31;
    int src = GATHER ? win_to_orig(warp) : warp;
    const float* ip = in + (size_t)src * CC;
    float v[6];
    float s = 0.f, s2 = 0.f;
#pragma unroll
    for (int k = 0; k < 6; k++) {
        v[k] = ip[lane + 32 * k];
        s += v[k]; s2 += v[k] * v[k];
    }
#pragma unroll
    for (int o = 16; o; o >>= 1) {
        s  += __shfl_xor_sync(0xffffffffu, s,  o);
        s2 += __shfl_xor_sync(0xffffffffu, s2, o);
    }
    float mean = s * (1.f / CC);
    float var  = s2 * (1.f / CC) - mean * mean;
    float rstd = rsqrtf(var + 1e-5f);
    float* op = out + (size_t)warp * CC;
#pragma unroll
    for (int k = 0; k < 6; k++) {
        int c = lane + 32 * k;
        op[c] = (v[k] - mean) * rstd * gg[c] + bb[c];
    }
}

// ================= tf32 mma.sync GEMM =================
// out[M,Ntot] = A[M,K] @ W[Ntot,K]^T + bias (+ epilogue)
// BM=128, BN=96, BK=32. 256 threads. Warp grid 4x2, warp tile 32x48.
#define BM 128
#define BN 96
#define BKF 32
#define SA 36
#define SB 36
#define ABUF (BM*SA)      // 4608 floats
#define BBUF (BN*SB)      // 3456 floats
#define BUFF (ABUF+BBUF)  // 8064 floats per stage
#define GSMEM (2*BUFF*4)  // 64512 bytes

template<int EPI>
__global__ __launch_bounds__(256)
void mma_gemm(const float* __restrict__ A, const float* __restrict__ W,
              const float* __restrict__ bias, float* __restrict__ out,
              const float* __restrict__ aux, int Ntot, int K) {
    extern __shared__ float sm[];
    int tid = threadIdx.x, lane = tid & 31, wid = tid >> 5;
    int m0 = blockIdx.y * BM, n0 = blockIdx.x * BN;
    int wm = (wid & 3) * 32, wn = (wid >> 2) * 48;
    int g = lane >> 2, t = lane & 3;

    float acc[2][6][4];
#pragma unroll
    for (int i = 0; i < 2; i++)
#pragma unroll
        for (int j = 0; j < 6; j++)
#pragma unroll
            for (int q = 0; q < 4; q++) acc[i][j][q] = 0.f;

    const float* Aptr = A + (size_t)m0 * K;
    const float* Wptr = W + (size_t)n0 * K;
    float4 ar[4], br[3];
    const int KC = K / BKF;

#define LDT(kc) { \
    const float* Ag = Aptr + (kc) * BKF; \
    const float* Wg = Wptr + (kc) * BKF; \
    _Pragma("unroll") for (int i2 = 0; i2 < 4; i2++) { int idx = tid + 256 * i2; \
        ar[i2] = *(const float4*)(Ag + (size_t)(idx >> 3) * K + (idx & 7) * 4); } \
    _Pragma("unroll") for (int i2 = 0; i2 < 3; i2++) { int idx = tid + 256 * i2; \
        br[i2] = *(const float4*)(Wg + (size_t)(idx >> 3) * K + (idx & 7) * 4); } }

#define STT(buf) { \
    float* Ab = sm + (buf) * BUFF; \
    float* Bb = Ab + ABUF; \
    _Pragma("unroll") for (int i2 = 0; i2 < 4; i2++) { int idx = tid + 256 * i2; \
        float* p = Ab + (idx >> 3) * SA + (idx & 7) * 4; \
        *(float4*)p = make_float4(__uint_as_float(f2tf32(ar[i2].x)), __uint_as_float(f2tf32(ar[i2].y)), \
                                  __uint_as_float(f2tf32(ar[i2].z)), __uint_as_float(f2tf32(ar[i2].w))); } \
    _Pragma("unroll") for (int i2 = 0; i2 < 3; i2++) { int idx = tid + 256 * i2; \
        float* p = Bb + (idx >> 3) * SB + (idx & 7) * 4; \
        *(float4*)p = make_float4(__uint_as_float(f2tf32(br[i2].x)), __uint_as_float(f2tf32(br[i2].y)), \
                                  __uint_as_float(f2tf32(br[i2].z)), __uint_as_float(f2tf32(br[i2].w))); } }

#define CMP(buf) { \
    const float* Ab = sm + (buf) * BUFF; \
    const float* Bb = Ab + ABUF; \
    _Pragma("unroll") for (int kk = 0; kk < BKF; kk += 8) { \
        uint32_t af[2][4]; uint32_t bf[6][2]; \
        _Pragma("unroll") for (int i2 = 0; i2 < 2; i2++) { \
            const float* ap = Ab + (wm + 16 * i2 + g) * SA + kk + t; \
            af[i2][0] = __float_as_uint(ap[0]); \
            af[i2][1] = __float_as_uint(ap[8 * SA]); \
            af[i2][2] = __float_as_uint(ap[4]); \
            af[i2][3] = __float_as_uint(ap[8 * SA + 4]); } \
        _Pragma("unroll") for (int j2 = 0; j2 < 6; j2++) { \
            const float* bp = Bb + (wn + 8 * j2 + g) * SB + kk + t; \
            bf[j2][0] = __float_as_uint(bp[0]); \
            bf[j2][1] = __float_as_uint(bp[4]); } \
        _Pragma("unroll") for (int i2 = 0; i2 < 2; i2++) \
            _Pragma("unroll") for (int j2 = 0; j2 < 6; j2++) \
                mma_tf32(acc[i2][j2], af[i2][0], af[i2][1], af[i2][2], af[i2][3], bf[j2][0], bf[j2][1]); } }

    LDT(0);
    STT(0);
    __syncthreads();
    for (int kc = 0; kc < KC; kc++) {
        if (kc + 1 < KC) LDT(kc + 1);
        CMP(kc & 1);
        if (kc + 1 < KC) {
            __syncthreads();
            STT((kc + 1) & 1);
            __syncthreads();
        }
    }

    // epilogue
#pragma unroll
    for (int i2 = 0; i2 < 2; i2++) {
#pragma unroll
        for (int half = 0; half < 2; half++) {
            int r = m0 + wm + 16 * i2 + g + 8 * half;
            size_t ob;
            if (EPI == 1)      ob = (size_t)win_to_orig(r) * CC;
            else if (EPI == 3) ob = (size_t)r * CC;
            else               ob = (size_t)r * Ntot;
#pragma unroll
            for (int j2 = 0; j2 < 6; j2++) {
                int c = n0 + wn + 8 * j2 + 2 * t;
                float v0 = acc[i2][j2][half * 2 + 0] + bias[c];
                float v1 = acc[i2][j2][half * 2 + 1] + bias[c + 1];
                if (EPI == 1 || EPI == 3) {
                    float2 a2 = *(const float2*)(aux + ob + c);
                    v0 += a2.x; v1 += a2.y;
                } else if (EPI == 2) {
                    v0 = 0.5f * v0 * (1.f + erff(v0 * 0.70710678118654752f));
                    v1 = 0.5f * v1 * (1.f + erff(v1 * 0.70710678118654752f));
                }
                *(float2*)(out + ob + c) = make_float2(v0, v1);
            }
        }
    }
#undef LDT
#undef STT
#undef CMP
}

// ================= Windowed attention =================
__global__ __launch_bounds__(64)
void attn_kernel(const float* __restrict__ qkv, const float* __restrict__ rpb,
                 float* __restrict__ outp) {
    int bidx = blockIdx.x;
    int head = bidx % HEADS;
    int w    = bidx / HEADS;
    int widx = w & 255;
    int wh = widx >> 4, ww = widx & 15;
    int i = threadIdx.x;

    __shared__ float ks[NN][HD];
    __shared__ float vs[NN][HD];

    size_t rowbase = ((size_t)w * NN + i) * C3;
    float qr[HD];
#pragma unroll
    for (int d = 0; d < HD; d += 4) {
        float4 qv = *(const float4*)(qkv + rowbase + head * HD + d);
        qr[d + 0] = qv.x * SCALE; qr[d + 1] = qv.y * SCALE;
        qr[d + 2] = qv.z * SCALE; qr[d + 3] = qv.w * SCALE;
    }
#pragma unroll
    for (int d = 0; d < HD; d += 4) {
        float4 kv = *(const float4*)(qkv + rowbase + CC + head * HD + d);
        ks[i][d + 0] = kv.x; ks[i][d + 1] = kv.y; ks[i][d + 2] = kv.z; ks[i][d + 3] = kv.w;
        float4 vv = *(const float4*)(qkv + rowbase + 2 * CC + head * HD + d);
        vs[i][d + 0] = vv.x; vs[i][d + 1] = vv.y; vs[i][d + 2] = vv.z; vs[i][d + 3] = vv.w;
    }
    __syncthreads();

    int ri = i >> 3, ci = i & 7;
    int gr = wh * 8 + ri, gc = ww * 8 + ci;
    int rh = (gr < HH - WS) ? 0 : ((gr < HH - SHIFTV) ? 1 : 2);
    int rw = (gc < WWID - WS) ? 0 : ((gc < WWID - SHIFTV) ? 1 : 2);
    int cnt_i = rh * 3 + rw;

    float s[NN];
#pragma unroll
    for (int j = 0; j < NN; j++) {
        float acc = 0.f;
#pragma unroll
        for (int d = 0; d < HD; d++) acc += qr[d] * ks[j][d];
        int rj = j >> 3, cj = j & 7;
        int idx = (ri - rj + 7) * 15 + (ci - cj + 7);
        acc += rpb[idx * HEADS + head];
        int gjr = wh * 8 + rj, gjc = ww * 8 + cj;
        int rhj = (gjr < HH - WS) ? 0 : ((gjr < HH - SHIFTV) ? 1 : 2);
        int rwj = (gjc < WWID - WS) ? 0 : ((gjc < WWID - SHIFTV) ? 1 : 2);
        if (rhj * 3 + rwj != cnt_i) acc += -100.0f;
        s[j] = acc;
    }
    float mx = -1e30f;
#pragma unroll
    for (int j = 0; j < NN; j++) mx = fmaxf(mx, s[j]);
    float sum = 0.f;
#pragma unroll
    for (int j = 0; j < NN; j++) { s[j] = __expf(s[j] - mx); sum += s[j]; }
    float inv = 1.f / sum;

    size_t obase = ((size_t)w * NN + i) * CC + head * HD;
#pragma unroll
    for (int d = 0; d < HD; d++) {
        float o = 0.f;
#pragma unroll
        for (int j = 0; j < NN; j++) o += s[j] * vs[j][d];
        outp[obase + d] = o * inv;
    }
}

// ================= host =================
extern "C" void kernel_launch(void* const* d_in, const int* in_sizes, int n_in,
                              void* d_out, int out_size) {
    const float* x     = (const float*)d_in[0];
    const float* n1g   = (const float*)d_in[1];
    const float* n1b   = (const float*)d_in[2];
    const float* qkvw  = (const float*)d_in[3];
    const float* qkvb  = (const float*)d_in[4];
    const float* projw = (const float*)d_in[5];
    const float* projb = (const float*)d_in[6];
    const float* rpb   = (const float*)d_in[7];
    const float* n2g   = (const float*)d_in[8];
    const float* n2b   = (const float*)d_in[9];
    const float* fc1w  = (const float*)d_in[10];
    const float* fc1b  = (const float*)d_in[11];
    const float* fc2w  = (const float*)d_in[12];
    const float* fc2b  = (const float*)d_in[13];
    float* out = (float*)d_out;

    float *xw, *qkv, *attn, *h, *m1;
    cudaGetSymbolAddress((void**)&xw,   g_xw);
    cudaGetSymbolAddress((void**)&qkv,  g_qkv);
    cudaGetSymbolAddress((void**)&attn, g_attn);
    cudaGetSymbolAddress((void**)&h,    g_h);
    cudaGetSymbolAddress((void**)&m1,   g_m1);

    cudaFuncSetAttribute(mma_gemm<0>, cudaFuncAttributeMaxDynamicSharedMemorySize, GSMEM);
    cudaFuncSetAttribute(mma_gemm<1>, cudaFuncAttributeMaxDynamicSharedMemorySize, GSMEM);
    cudaFuncSetAttribute(mma_gemm<2>, cudaFuncAttributeMaxDynamicSharedMemorySize, GSMEM);
    cudaFuncSetAttribute(mma_gemm<3>, cudaFuncAttributeMaxDynamicSharedMemorySize, GSMEM);

    // 1. LN1 + shift + window partition
    ln_kernel<1><<<TT / 8, 256>>>(x, n1g, n1b, xw);
    // 2. QKV: [T,192] x [576,192]^T
    mma_gemm<0><<<dim3(C3 / BN, TT / BM), 256, GSMEM>>>(xw, qkvw, qkvb, qkv, nullptr, C3, CC);
    // 3. Attention
    attn_kernel<<<BWIN * HEADS, 64>>>(qkv, rpb, attn);
    // 4. Proj + window reverse + unshift + residual(x)
    mma_gemm<1><<<dim3(CC / BN, TT / BM), 256, GSMEM>>>(attn, projw, projb, h, x, CC, CC);
    // 5. LN2
    ln_kernel<0><<<TT / 8, 256>>>(h, n2g, n2b, xw);
    // 6. FC1 + GELU
    mma_gemm<2><<<dim3(C4 / BN, TT / BM), 256, GSMEM>>>(xw, fc1w, fc1b, m1, nullptr, C4, CC);
    // 7. FC2 + residual(h)
    mma_gemm<3><<<dim3(CC / BN, TT / BM), 256, GSMEM>>>(m1, fc2w, fc2b, out, h, CC, C4);
}

// round 4
// speedup vs baseline: 2.9288x; 1.2554x over previous
#include <cuda_runtime.h>
#include <cuda_bf16.h>
#include <cstdint>
#include <math.h>

// ---- problem constants ----
#define BB    16
#define HH    128
#define WWID  128
#define CC    192
#define WS    8
#define SHIFTV 4
#define HEADS 6
#define NN    64
#define HD    32
#define TT    (BB*HH*WWID)   // 262144
#define NWIN  256
#define BWIN  (BB*NWIN)      // 4096
#define C3    (3*CC)         // 576
#define C4    (4*CC)         // 768
#define SCALE 0.17677669529663687f

// ---- scratch (bf16 intermediates, fp32 trunk) ----
__device__ __align__(16) __nv_bfloat16 g_xw  [(size_t)TT*CC];
__device__ __align__(16) __nv_bfloat16 g_qkv [(size_t)TT*C3];
__device__ __align__(16) __nv_bfloat16 g_attn[(size_t)TT*CC];
__device__ __align__(16) float         g_h   [(size_t)TT*CC];
__device__ __align__(16) __nv_bfloat16 g_m1  [(size_t)TT*C4];

// ---- helpers ----
__device__ __forceinline__ uint32_t smem_u32(const void* p) {
    uint32_t a;
    asm("{ .reg .u64 t; cvta.to.shared.u64 t, %1; cvt.u32.u64 %0, t; }" : "=r"(a) : "l"(p));
    return a;
}
__device__ __forceinline__ uint32_t packbf2(float lo, float hi) {
    uint32_t r;
    asm("cvt.rn.bf16x2.f32 %0, %1, %2;" : "=r"(r) : "f"(hi), "f"(lo));
    return r;
}
__device__ __forceinline__ void ldm4(uint32_t r[4], uint32_t addr) {
    asm volatile("ldmatrix.sync.aligned.m8n8.x4.shared.b16 {%0,%1,%2,%3}, [%4];"
        : "=r"(r[0]), "=r"(r[1]), "=r"(r[2]), "=r"(r[3]) : "r"(addr));
}
__device__ __forceinline__ void mma_bf16(float c[4], const uint32_t a[4], uint32_t b0, uint32_t b1) {
    asm volatile("mma.sync.aligned.m16n8k16.row.col.f32.bf16.bf16.f32 "
        "{%0,%1,%2,%3},{%4,%5,%6,%7},{%8,%9},{%0,%1,%2,%3};"
        : "+f"(c[0]), "+f"(c[1]), "+f"(c[2]), "+f"(c[3])
        : "r"(a[0]), "r"(a[1]), "r"(a[2]), "r"(a[3]), "r"(b0), "r"(b1));
}
__device__ __forceinline__ int win_to_orig(int tw) {
    int n  = tw & 63;
    int bw = tw >> 6;
    int ww = bw & 15;
    int wh = (bw >> 4) & 15;
    int b  = bw >> 8;
    int ri = n >> 3, ci = n & 7;
    int r = (wh * 8 + ri + SHIFTV) & 127;
    int c = (ww * 8 + ci + SHIFTV) & 127;
    return (b << 14) + (r << 7) + c;
}
__device__ __forceinline__ void bf8_to_f(uint4 u, float* f) {
    float2 a = __bfloat1622float2(*(__nv_bfloat162*)&u.x);
    float2 b = __bfloat1622float2(*(__nv_bfloat162*)&u.y);
    float2 c = __bfloat1622float2(*(__nv_bfloat162*)&u.z);
    float2 d = __bfloat1622float2(*(__nv_bfloat162*)&u.w);
    f[0] = a.x; f[1] = a.y; f[2] = b.x; f[3] = b.y;
    f[4] = c.x; f[5] = c.y; f[6] = d.x; f[7] = d.y;
}

// ================= LayerNorm (fp32 in -> bf16 out) =================
template<int GATHER>
__global__ void ln_kernel(const float* __restrict__ in, const float* __restrict__ gg,
                          const float* __restrict__ bb, __nv_bfloat16* __restrict__ out) {
    int warp = blockIdx.x * (blockDim.x >> 5) + (threadIdx.x >> 5);
    int lane = threadIdx.x & 31;
    int src = GATHER ? win_to_orig(warp) : warp;
    const float* ip = in + (size_t)src * CC;
    float v[6];
    float s = 0.f, s2 = 0.f;
#pragma unroll
    for (int k = 0; k < 6; k++) {
        v[k] = ip[lane + 32 * k];
        s += v[k]; s2 += v[k] * v[k];
    }
#pragma unroll
    for (int o = 16; o; o >>= 1) {
        s  += __shfl_xor_sync(0xffffffffu, s,  o);
        s2 += __shfl_xor_sync(0xffffffffu, s2, o);
    }
    float mean = s * (1.f / CC);
    float var  = s2 * (1.f / CC) - mean * mean;
    float rstd = rsqrtf(var + 1e-5f);
    __nv_bfloat16* op = out + (size_t)warp * CC;
#pragma unroll
    for (int k = 0; k < 6; k++) {
        int c = lane + 32 * k;
        op[c] = __float2bfloat16((v[k] - mean) * rstd * gg[c] + bb[c]);
    }
}

// ================= bf16 mma GEMM =================
// out[M,Ntot] = A[M,K](bf16) @ W[Ntot,K](fp32->bf16)^T + bias (+ epilogue)
// BM=128, BN=96, BK=64 halves. 256 threads, warp grid 4x2, warp tile 32x48.
#define BM 128
#define BN 96
#define BKH 64
#define AST (BM*128)          // 16384 B per A stage
#define BST (BN*128)          // 12288 B per B stage
#define STAGE (AST+BST)       // 28672
#define GSMEM (2*STAGE)       // 57344

// EPI: 0 qkv (bf16 out), 1 proj (+x, scatter, f32 out), 2 fc1 gelu (bf16 out), 3 fc2 (+h, f32 out)
template<int EPI>
__global__ __launch_bounds__(256)
void bgemm(const __nv_bfloat16* __restrict__ A, const float* __restrict__ W,
           const float* __restrict__ bias, void* __restrict__ outv,
           const float* __restrict__ aux, int Ntot, int K) {
    extern __shared__ char smc[];
    uint32_t sbase = smem_u32(smc);
    int tid = threadIdx.x, lane = tid & 31, wid = tid >> 5;
    int m0 = blockIdx.y * BM, n0 = blockIdx.x * BN;
    int wm = (wid & 3) * 32, wn = (wid >> 2) * 48;
    int g = lane >> 2, t = lane & 3;

    float acc[2][6][4];
#pragma unroll
    for (int i = 0; i < 2; i++)
#pragma unroll
        for (int j = 0; j < 6; j++)
#pragma unroll
            for (int q = 0; q < 4; q++) acc[i][j][q] = 0.f;

    const __nv_bfloat16* Abp = A + (size_t)m0 * K;
    const float* Wbp = W + (size_t)n0 * K;
    uint4 areg[4], breg[3];

    // per-lane ldmatrix geometry
    int l8 = lane & 7;
    int msel = lane >> 3;                 // 0..3
    int arow0 = wm + l8 + ((msel & 1) << 3);
    int aco   = msel >> 1;
    int brow0 = wn + l8 + ((msel >> 1) << 3);
    int bco   = msel & 1;

#define LDT(kt) { \
    _Pragma("unroll") for (int i2 = 0; i2 < 4; i2++) { int id = tid + 256 * i2; \
        int row = id >> 3, cc_ = id & 7; \
        areg[i2] = *(const uint4*)(Abp + (size_t)row * K + (kt) * BKH + cc_ * 8); } \
    _Pragma("unroll") for (int i2 = 0; i2 < 3; i2++) { int id = tid + 256 * i2; \
        int row = id >> 3, cc_ = id & 7; \
        const float* wp = Wbp + (size_t)row * K + (kt) * BKH + cc_ * 8; \
        float4 f0 = *(const float4*)wp; float4 f1 = *(const float4*)(wp + 4); \
        breg[i2] = make_uint4(packbf2(f0.x, f0.y), packbf2(f0.z, f0.w), \
                              packbf2(f1.x, f1.y), packbf2(f1.z, f1.w)); } }

#define STT(buf) { \
    char* As_ = smc + (buf) * STAGE; \
    char* Bs_ = As_ + AST; \
    _Pragma("unroll") for (int i2 = 0; i2 < 4; i2++) { int id = tid + 256 * i2; \
        int row = id >> 3, cc_ = id & 7; \
        *(uint4*)(As_ + row * 128 + ((cc_ ^ (row & 7)) * 16)) = areg[i2]; } \
    _Pragma("unroll") for (int i2 = 0; i2 < 3; i2++) { int id = tid + 256 * i2; \
        int row = id >> 3, cc_ = id & 7; \
        *(uint4*)(Bs_ + row * 128 + ((cc_ ^ (row & 7)) * 16)) = breg[i2]; } }

#define CMP(buf) { \
    uint32_t sA = sbase + (buf) * STAGE; \
    uint32_t sB = sA + AST; \
    _Pragma("unroll") for (int s = 0; s < 4; s++) { \
        uint32_t af[2][4], bf[3][4]; \
        _Pragma("unroll") for (int i2 = 0; i2 < 2; i2++) \
            ldm4(af[i2], sA + (uint32_t)(arow0 + 16 * i2) * 128 + (uint32_t)(((2 * s + aco) ^ l8) * 16)); \
        _Pragma("unroll") for (int j = 0; j < 3; j++) \
            ldm4(bf[j], sB + (uint32_t)(brow0 + 16 * j) * 128 + (uint32_t)(((2 * s + bco) ^ l8) * 16)); \
        _Pragma("unroll") for (int i2 = 0; i2 < 2; i2++) \
            _Pragma("unroll") for (int j = 0; j < 3; j++) { \
                mma_bf16(acc[i2][2 * j + 0], af[i2], bf[j][0], bf[j][1]); \
                mma_bf16(acc[i2][2 * j + 1], af[i2], bf[j][2], bf[j][3]); } } }

    const int KT = K / BKH;
    LDT(0);
    STT(0);
    __syncthreads();
    for (int kt = 0; kt < KT; kt++) {
        if (kt + 1 < KT) LDT(kt + 1);
        CMP(kt & 1);
        if (kt + 1 < KT) {
            __syncthreads();
            STT((kt + 1) & 1);
            __syncthreads();
        }
    }
#undef LDT
#undef STT
#undef CMP

    // ---- epilogue ----
#pragma unroll
    for (int i2 = 0; i2 < 2; i2++) {
#pragma unroll
        for (int half = 0; half < 2; half++) {
            int r = m0 + wm + 16 * i2 + g + 8 * half;
            size_t ob;
            if (EPI == 1)      ob = (size_t)win_to_orig(r) * CC;
            else if (EPI == 3) ob = (size_t)r * CC;
            else               ob = (size_t)r * Ntot;
#pragma unroll
            for (int j2 = 0; j2 < 6; j2++) {
                int c = n0 + wn + 8 * j2 + 2 * t;
                float v0 = acc[i2][j2][half * 2 + 0] + bias[c];
                float v1 = acc[i2][j2][half * 2 + 1] + bias[c + 1];
                if (EPI == 1 || EPI == 3) {
                    float2 a2 = *(const float2*)(aux + ob + c);
                    v0 += a2.x; v1 += a2.y;
                    *(float2*)((float*)outv + ob + c) = make_float2(v0, v1);
                } else if (EPI == 2) {
                    v0 = 0.5f * v0 * (1.f + erff(v0 * 0.70710678118654752f));
                    v1 = 0.5f * v1 * (1.f + erff(v1 * 0.70710678118654752f));
                    *(uint32_t*)((__nv_bfloat16*)outv + ob + c) = packbf2(v0, v1);
                } else {
                    *(uint32_t*)((__nv_bfloat16*)outv + ob + c) = packbf2(v0, v1);
                }
            }
        }
    }
}

// ================= Windowed attention (bf16 io, fp32 compute) =================
__global__ __launch_bounds__(64)
void attn_kernel(const __nv_bfloat16* __restrict__ qkv, const float* __restrict__ rpb,
                 __nv_bfloat16* __restrict__ outp) {
    int bidx = blockIdx.x;
    int head = bidx % HEADS;
    int w    = bidx / HEADS;
    int widx = w & 255;
    int wh = widx >> 4, ww = widx & 15;
    int i = threadIdx.x;

    __shared__ float ks[NN][HD];
    __shared__ float vs[NN][HD];

    size_t rowbase = ((size_t)w * NN + i) * C3;
    float qr[HD];
#pragma unroll
    for (int c = 0; c < 4; c++) {
        uint4 u = *(const uint4*)(qkv + rowbase + head * HD + c * 8);
        float f[8]; bf8_to_f(u, f);
#pragma unroll
        for (int d = 0; d < 8; d++) qr[c * 8 + d] = f[d] * SCALE;
    }
#pragma unroll
    for (int c = 0; c < 4; c++) {
        uint4 uk = *(const uint4*)(qkv + rowbase + CC + head * HD + c * 8);
        uint4 uv = *(const uint4*)(qkv + rowbase + 2 * CC + head * HD + c * 8);
        float fk[8], fv[8]; bf8_to_f(uk, fk); bf8_to_f(uv, fv);
#pragma unroll
        for (int d = 0; d < 8; d++) { ks[i][c * 8 + d] = fk[d]; vs[i][c * 8 + d] = fv[d]; }
    }
    __syncthreads();

    int ri = i >> 3, ci = i & 7;
    int gr = wh * 8 + ri, gc = ww * 8 + ci;
    int rh = (gr < HH - WS) ? 0 : ((gr < HH - SHIFTV) ? 1 : 2);
    int rw = (gc < WWID - WS) ? 0 : ((gc < WWID - SHIFTV) ? 1 : 2);
    int cnt_i = rh * 3 + rw;

    float s[NN];
#pragma unroll
    for (int j = 0; j < NN; j++) {
        float acc = 0.f;
#pragma unroll
        for (int d = 0; d < HD; d++) acc += qr[d] * ks[j][d];
        int rj = j >> 3, cj = j & 7;
        int idx = (ri - rj + 7) * 15 + (ci - cj + 7);
        acc += rpb[idx * HEADS + head];
        int gjr = wh * 8 + rj, gjc = ww * 8 + cj;
        int rhj = (gjr < HH - WS) ? 0 : ((gjr < HH - SHIFTV) ? 1 : 2);
        int rwj = (gjc < WWID - WS) ? 0 : ((gjc < WWID - SHIFTV) ? 1 : 2);
        if (rhj * 3 + rwj != cnt_i) acc += -100.0f;
        s[j] = acc;
    }
    float mx = -1e30f;
#pragma unroll
    for (int j = 0; j < NN; j++) mx = fmaxf(mx, s[j]);
    float sum = 0.f;
#pragma unroll
    for (int j = 0; j < NN; j++) { s[j] = __expf(s[j] - mx); sum += s[j]; }
    float inv = 1.f / sum;

    size_t obase = ((size_t)w * NN + i) * CC + head * HD;
#pragma unroll
    for (int d = 0; d < HD; d += 2) {
        float o0 = 0.f, o1 = 0.f;
#pragma unroll
        for (int j = 0; j < NN; j++) {
            o0 += s[j] * vs[j][d];
            o1 += s[j] * vs[j][d + 1];
        }
        *(uint32_t*)(outp + obase + d) = packbf2(o0 * inv, o1 * inv);
    }
}

// ================= host =================
extern "C" void kernel_launch(void* const* d_in, const int* in_sizes, int n_in,
                              void* d_out, int out_size) {
    const float* x     = (const float*)d_in[0];
    const float* n1g   = (const float*)d_in[1];
    const float* n1b   = (const float*)d_in[2];
    const float* qkvw  = (const float*)d_in[3];
    const float* qkvb  = (const float*)d_in[4];
    const float* projw = (const float*)d_in[5];
    const float* projb = (const float*)d_in[6];
    const float* rpb   = (const float*)d_in[7];
    const float* n2g   = (const float*)d_in[8];
    const float* n2b   = (const float*)d_in[9];
    const float* fc1w  = (const float*)d_in[10];
    const float* fc1b  = (const float*)d_in[11];
    const float* fc2w  = (const float*)d_in[12];
    const float* fc2b  = (const float*)d_in[13];
    float* out = (float*)d_out;

    __nv_bfloat16 *xw, *qkv, *attn, *m1;
    float *h;
    cudaGetSymbolAddress((void**)&xw,   g_xw);
    cudaGetSymbolAddress((void**)&qkv,  g_qkv);
    cudaGetSymbolAddress((void**)&attn, g_attn);
    cudaGetSymbolAddress((void**)&h,    g_h);
    cudaGetSymbolAddress((void**)&m1,   g_m1);

    cudaFuncSetAttribute(bgemm<0>, cudaFuncAttributeMaxDynamicSharedMemorySize, GSMEM);
    cudaFuncSetAttribute(bgemm<1>, cudaFuncAttributeMaxDynamicSharedMemorySize, GSMEM);
    cudaFuncSetAttribute(bgemm<2>, cudaFuncAttributeMaxDynamicSharedMemorySize, GSMEM);
    cudaFuncSetAttribute(bgemm<3>, cudaFuncAttributeMaxDynamicSharedMemorySize, GSMEM);

    // 1. LN1 + shift + window partition (fp32 -> bf16)
    ln_kernel<1><<<TT / 8, 256>>>(x, n1g, n1b, xw);
    // 2. QKV: [T,192]bf16 x [576,192]^T
    bgemm<0><<<dim3(C3 / BN, TT / BM), 256, GSMEM>>>(xw, qkvw, qkvb, qkv, nullptr, C3, CC);
    // 3. Attention
    attn_kernel<<<BWIN * HEADS, 64>>>(qkv, rpb, attn);
    // 4. Proj + window reverse + unshift + residual(x) -> h fp32
    bgemm<1><<<dim3(CC / BN, TT / BM), 256, GSMEM>>>(attn, projw, projb, h, x, CC, CC);
    // 5. LN2 (h fp32 -> bf16)
    ln_kernel<0><<<TT / 8, 256>>>(h, n2g, n2b, xw);
    // 6. FC1 + GELU (bf16 out)
    bgemm<2><<<dim3(C4 / BN, TT / BM), 256, GSMEM>>>(xw, fc1w, fc1b, m1, nullptr, C4, CC);
    // 7. FC2 + residual(h) -> out fp32
    bgemm<3><<<dim3(CC / BN, TT / BM), 256, GSMEM>>>(m1, fc2w, fc2b, out, h, CC, C4);
}

// round 5
// speedup vs baseline: 4.4578x; 1.5220x over previous
#include <cuda_runtime.h>
#include <cuda_bf16.h>
#include <cstdint>
#include <math.h>

// ---- problem constants ----
#define BB    16
#define HH    128
#define WWID  128
#define CC    192
#define WS    8
#define SHIFTV 4
#define HEADS 6
#define NN    64
#define HD    32
#define TT    (BB*HH*WWID)   // 262144
#define NWIN  256
#define BWIN  (BB*NWIN)      // 4096
#define C3    (3*CC)         // 576
#define C4    (4*CC)         // 768
#define SCALE 0.17677669529663687f

// ---- scratch ----
__device__ __align__(16) __nv_bfloat16 g_xw  [(size_t)TT*CC];
__device__ __align__(16) __nv_bfloat16 g_qkv [(size_t)TT*C3];
__device__ __align__(16) __nv_bfloat16 g_attn[(size_t)TT*CC];
__device__ __align__(16) float         g_h   [(size_t)TT*CC];
__device__ __align__(16) __nv_bfloat16 g_m1  [(size_t)TT*C4];
__device__ __align__(16) __nv_bfloat16 g_wb  [C3*CC + CC*CC + C4*CC + CC*C4];  // bf16 weights

#define WB_QKV  0
#define WB_PROJ (C3*CC)                    // 110592
#define WB_FC1  (WB_PROJ + CC*CC)          // 147456
#define WB_FC2  (WB_FC1 + C4*CC)           // 294912

// ---- helpers ----
__device__ __forceinline__ uint32_t smem_u32(const void* p) {
    uint32_t a;
    asm("{ .reg .u64 t; cvta.to.shared.u64 t, %1; cvt.u32.u64 %0, t; }" : "=r"(a) : "l"(p));
    return a;
}
__device__ __forceinline__ uint32_t packbf2(float lo, float hi) {
    uint32_t r;
    asm("cvt.rn.bf16x2.f32 %0, %1, %2;" : "=r"(r) : "f"(hi), "f"(lo));
    return r;
}
__device__ __forceinline__ void ldm4(uint32_t r[4], uint32_t addr) {
    asm volatile("ldmatrix.sync.aligned.m8n8.x4.shared.b16 {%0,%1,%2,%3}, [%4];"
        : "=r"(r[0]), "=r"(r[1]), "=r"(r[2]), "=r"(r[3]) : "r"(addr));
}
__device__ __forceinline__ void ldm4t(uint32_t r[4], uint32_t addr) {
    asm volatile("ldmatrix.sync.aligned.m8n8.x4.trans.shared.b16 {%0,%1,%2,%3}, [%4];"
        : "=r"(r[0]), "=r"(r[1]), "=r"(r[2]), "=r"(r[3]) : "r"(addr));
}
__device__ __forceinline__ void mma_bf16(float c[4], const uint32_t a[4], uint32_t b0, uint32_t b1) {
    asm volatile("mma.sync.aligned.m16n8k16.row.col.f32.bf16.bf16.f32 "
        "{%0,%1,%2,%3},{%4,%5,%6,%7},{%8,%9},{%0,%1,%2,%3};"
        : "+f"(c[0]), "+f"(c[1]), "+f"(c[2]), "+f"(c[3])
        : "r"(a[0]), "r"(a[1]), "r"(a[2]), "r"(a[3]), "r"(b0), "r"(b1));
}
#define CP16(dst, src) asm volatile("cp.async.cg.shared.global [%0], [%1], 16;" :: "r"(dst), "l"(src))
#define CPCA16(dst, src) asm volatile("cp.async.ca.shared.global [%0], [%1], 16;" :: "r"(dst), "l"(src))
#define CP4(dst, src)  asm volatile("cp.async.ca.shared.global [%0], [%1], 4;"  :: "r"(dst), "l"(src))
#define CPCOMMIT() asm volatile("cp.async.commit_group;" ::: "memory")
#define CPWAIT(n)  asm volatile("cp.async.wait_group %0;" :: "n"(n) : "memory")

__device__ __forceinline__ int win_to_orig(int tw) {
    int n  = tw & 63;
    int bw = tw >> 6;
    int ww = bw & 15;
    int wh = (bw >> 4) & 15;
    int b  = bw >> 8;
    int ri = n >> 3, ci = n & 7;
    int r = (wh * 8 + ri + SHIFTV) & 127;
    int c = (ww * 8 + ci + SHIFTV) & 127;
    return (b << 14) + (r << 7) + c;
}

// ================= weight convert (fp32 -> bf16) =================
__global__ void wconv(const float* __restrict__ src, __nv_bfloat16* __restrict__ dst, int n) {
    int i = blockIdx.x * 256 + threadIdx.x;
    if (i * 4 < n) {
        float4 f = *(const float4*)(src + i * 4);
        uint2 u = make_uint2(packbf2(f.x, f.y), packbf2(f.z, f.w));
        *(uint2*)(dst + i * 4) = u;
    }
}

// ================= LayerNorm (fp32 in -> bf16 out) =================
template<int GATHER>
__global__ void ln_kernel(const float* __restrict__ in, const float* __restrict__ gg,
                          const float* __restrict__ bb, __nv_bfloat16* __restrict__ out) {
    int warp = blockIdx.x * (blockDim.x >> 5) + (threadIdx.x >> 5);
    int lane = threadIdx.x & 31;
    int src = GATHER ? win_to_orig(warp) : warp;
    const float* ip = in + (size_t)src * CC;
    float v[6];
    float s = 0.f, s2 = 0.f;
#pragma unroll
    for (int k = 0; k < 6; k++) {
        v[k] = ip[lane + 32 * k];
        s += v[k]; s2 += v[k] * v[k];
    }
#pragma unroll
    for (int o = 16; o; o >>= 1) {
        s  += __shfl_xor_sync(0xffffffffu, s,  o);
        s2 += __shfl_xor_sync(0xffffffffu, s2, o);
    }
    float mean = s * (1.f / CC);
    float var  = s2 * (1.f / CC) - mean * mean;
    float rstd = rsqrtf(var + 1e-5f);
    __nv_bfloat16* op = out + (size_t)warp * CC;
#pragma unroll
    for (int k = 0; k < 6; k++) {
        int c = lane + 32 * k;
        op[c] = __float2bfloat16((v[k] - mean) * rstd * gg[c] + bb[c]);
    }
}

// ================= bf16 mma GEMM (cp.async, warp tile 64x48) =================
// out[M,Ntot] = A[M,K](bf16) @ W[Ntot,K](bf16)^T + bias (+ epilogue)
// BM=128, BN=192, BK=64 halves; 256 threads; warp grid 2x4; warp tile 64x48.
#define BM 128
#define BN 192
#define BKH 64
#define AST (BM*128)          // 16384 B
#define BST (BN*128)          // 24576 B
#define STAGE (AST+BST)       // 40960
#define GSMEM (2*STAGE)       // 81920

template<int EPI>
__global__ __launch_bounds__(256)
void bgemm(const __nv_bfloat16* __restrict__ A, const __nv_bfloat16* __restrict__ W,
           const float* __restrict__ bias, void* __restrict__ outv,
           const float* __restrict__ aux, int Ntot, int K) {
    extern __shared__ char smc[];
    uint32_t sbase = smem_u32(smc);
    int tid = threadIdx.x, lane = tid & 31, wid = tid >> 5;
    int m0 = blockIdx.y * BM, n0 = blockIdx.x * BN;
    int wm = (wid & 1) * 64, wn = (wid >> 1) * 48;
    int g = lane >> 2, t = lane & 3;
    int l8 = lane & 7, msel = lane >> 3;

    float acc[4][6][4];
#pragma unroll
    for (int i = 0; i < 4; i++)
#pragma unroll
        for (int j = 0; j < 6; j++)
#pragma unroll
            for (int q = 0; q < 4; q++) acc[i][j][q] = 0.f;

    const __nv_bfloat16* Abp = A + (size_t)m0 * K;
    const __nv_bfloat16* Wbp = W + (size_t)n0 * K;

#define ISSUE(kt, buf) { \
    uint32_t sA_ = sbase + (buf) * STAGE; \
    uint32_t sB_ = sA_ + AST; \
    _Pragma("unroll") for (int i2 = 0; i2 < 4; i2++) { int id = tid + 256 * i2; \
        int row = id >> 3, cc_ = id & 7; \
        CP16(sA_ + (uint32_t)(row * 128 + ((cc_ ^ (row & 7)) * 16)), \
             Abp + (size_t)row * K + (kt) * BKH + cc_ * 8); } \
    _Pragma("unroll") for (int i2 = 0; i2 < 6; i2++) { int id = tid + 256 * i2; \
        int row = id >> 3, cc_ = id & 7; \
        CPCA16(sB_ + (uint32_t)(row * 128 + ((cc_ ^ (row & 7)) * 16)), \
             Wbp + (size_t)row * K + (kt) * BKH + cc_ * 8); } \
    CPCOMMIT(); }

#define CMP(buf) { \
    uint32_t sA_ = sbase + (buf) * STAGE; \
    uint32_t sB_ = sA_ + AST; \
    _Pragma("unroll") for (int s = 0; s < 4; s++) { \
        uint32_t af[4][4]; \
        _Pragma("unroll") for (int i2 = 0; i2 < 4; i2++) \
            ldm4(af[i2], sA_ + (uint32_t)(wm + 16 * i2 + l8 + ((msel & 1) << 3)) * 128 \
                             + (uint32_t)(((2 * s + (msel >> 1)) ^ l8) * 16)); \
        _Pragma("unroll") for (int j = 0; j < 3; j++) { \
            uint32_t bq[4]; \
            ldm4(bq, sB_ + (uint32_t)(wn + 16 * j + l8 + ((msel >> 1) << 3)) * 128 \
                         + (uint32_t)(((2 * s + (msel & 1)) ^ l8) * 16)); \
            _Pragma("unroll") for (int i2 = 0; i2 < 4; i2++) { \
                mma_bf16(acc[i2][2 * j + 0], af[i2], bq[0], bq[1]); \
                mma_bf16(acc[i2][2 * j + 1], af[i2], bq[2], bq[3]); } } } }

    const int KT = K / BKH;
    ISSUE(0, 0);
    for (int kt = 0; kt < KT; kt++) {
        if (kt + 1 < KT) { ISSUE(kt + 1, (kt + 1) & 1); CPWAIT(1); }
        else             { CPWAIT(0); }
        __syncthreads();
        CMP(kt & 1);
        __syncthreads();
    }
#undef ISSUE
#undef CMP

    // ---- epilogue ----
#pragma unroll
    for (int i2 = 0; i2 < 4; i2++) {
#pragma unroll
        for (int half = 0; half < 2; half++) {
            int r = m0 + wm + 16 * i2 + g + 8 * half;
            size_t ob;
            if (EPI == 1)      ob = (size_t)win_to_orig(r) * CC;
            else if (EPI == 3) ob = (size_t)r * CC;
            else               ob = (size_t)r * Ntot;
#pragma unroll
            for (int j2 = 0; j2 < 6; j2++) {
                int c = n0 + wn + 8 * j2 + 2 * t;
                float v0 = acc[i2][j2][half * 2 + 0] + bias[c];
                float v1 = acc[i2][j2][half * 2 + 1] + bias[c + 1];
                if (EPI == 1 || EPI == 3) {
                    float2 a2 = *(const float2*)(aux + ob + c);
                    v0 += a2.x; v1 += a2.y;
                    *(float2*)((float*)outv + ob + c) = make_float2(v0, v1);
                } else if (EPI == 2) {
                    v0 = 0.5f * v0 * (1.f + erff(v0 * 0.70710678118654752f));
                    v1 = 0.5f * v1 * (1.f + erff(v1 * 0.70710678118654752f));
                    *(uint32_t*)((__nv_bfloat16*)outv + ob + c) = packbf2(v0, v1);
                } else {
                    *(uint32_t*)((__nv_bfloat16*)outv + ob + c) = packbf2(v0, v1);
                }
            }
        }
    }
}

// ================= Tensor-core windowed attention =================
// Block = 1 window; 384 threads = 12 warps = 6 heads x 2 row-halves.
// smem: Q/K/V per head [64 rows][40 halves] (80B stride, conflict-free), + rpb table.
#define AT_THREADS 384
#define AT_SLOT    2560                       // halves per (tensor,head)
#define AT_RPB_OFF (18*AT_SLOT*2)             // 92160 B
#define AT_SMEM    (AT_RPB_OFF + 1350*4)      // 97560 B

__global__ __launch_bounds__(AT_THREADS)
void attn_mma(const __nv_bfloat16* __restrict__ qkv, const float* __restrict__ rpb,
              __nv_bfloat16* __restrict__ outp) {
    extern __shared__ char sm[];
    uint32_t sb = smem_u32(sm);
    int w = blockIdx.x;
    int widx = w & 255;
    int wh = widx >> 4, ww = widx & 15;
    int tid = threadIdx.x, lane = tid & 31, wid = tid >> 5;

    // stage qkv for this window: 18 slots x 64 rows x 4 chunks(16B)
    const __nv_bfloat16* src = qkv + (size_t)w * NN * C3;
    for (int idx = tid; idx < 4608; idx += AT_THREADS) {
        int slot = idx >> 8;
        int rem = idx & 255;
        int row = rem >> 2, c = rem & 3;
        int tt = slot / 6, hh = slot - tt * 6;
        uint32_t dst = sb + (uint32_t)(slot * AT_SLOT + row * 40) * 2 + c * 16;
        CPCA16(dst, src + (size_t)row * C3 + tt * CC + hh * HD + c * 8);
    }
    for (int idx = tid; idx < 1350; idx += AT_THREADS)
        CP4(sb + AT_RPB_OFF + idx * 4, rpb + idx);
    CPCOMMIT();
    CPWAIT(0);
    __syncthreads();

    int h = wid >> 1, half = wid & 1;
    uint32_t Qb = sb + (uint32_t)(0 * 6 + h) * AT_SLOT * 2;
    uint32_t Kb = sb + (uint32_t)(1 * 6 + h) * AT_SLOT * 2;
    uint32_t Vb = sb + (uint32_t)(2 * 6 + h) * AT_SLOT * 2;
    const float* rpbs = (const float*)(sm + AT_RPB_OFF);
    int l8 = lane & 7, msel = lane >> 3;
    int g = lane >> 2, t4 = lane & 3;

    // ---- S = Q @ K^T ----
    uint32_t qf[2][2][4];
#pragma unroll
    for (int mi = 0; mi < 2; mi++)
#pragma unroll
        for (int kt = 0; kt < 2; kt++)
            ldm4(qf[mi][kt], Qb + (uint32_t)(half * 32 + 16 * mi + l8 + ((msel & 1) << 3)) * 80
                                + (uint32_t)(kt * 32 + (msel >> 1) * 16));

    float s[2][8][4];
#pragma unroll
    for (int mi = 0; mi < 2; mi++)
#pragma unroll
        for (int n2 = 0; n2 < 8; n2++)
#pragma unroll
            for (int e = 0; e < 4; e++) s[mi][n2][e] = 0.f;

#pragma unroll
    for (int nj = 0; nj < 4; nj++) {
#pragma unroll
        for (int kt = 0; kt < 2; kt++) {
            uint32_t kf[4];
            ldm4(kf, Kb + (uint32_t)(nj * 16 + l8 + ((msel >> 1) << 3)) * 80
                        + (uint32_t)(kt * 32 + (msel & 1) * 16));
#pragma unroll
            for (int mi = 0; mi < 2; mi++) {
                mma_bf16(s[mi][2 * nj + 0], qf[mi][kt], kf[0], kf[1]);
                mma_bf16(s[mi][2 * nj + 1], qf[mi][kt], kf[2], kf[3]);
            }
        }
    }

    // ---- bias + mask + softmax (per row, cols split across quad) ----
#pragma unroll
    for (int mi = 0; mi < 2; mi++) {
        int r0 = half * 32 + 16 * mi + g;
#pragma unroll
        for (int e = 0; e < 4; e++) {
            int rowv = r0 + (e >> 1) * 8;
            int ri = rowv >> 3, ci = rowv & 7;
            int gi_r = wh * 8 + ri, gi_c = ww * 8 + ci;
            int clsI = ((gi_r < HH - WS) ? 0 : ((gi_r < HH - SHIFTV) ? 1 : 2)) * 3
                     + ((gi_c < WWID - WS) ? 0 : ((gi_c < WWID - SHIFTV) ? 1 : 2));
#pragma unroll
            for (int n2 = 0; n2 < 8; n2++) {
                int col = 8 * n2 + 2 * t4 + (e & 1);
                int rj = col >> 3, cj = col & 7;
                float b = rpbs[((ri - rj + 7) * 15 + (ci - cj + 7)) * HEADS + h];
                int gj_r = wh * 8 + rj, gj_c = ww * 8 + cj;
                int clsJ = ((gj_r < HH - WS) ? 0 : ((gj_r < HH - SHIFTV) ? 1 : 2)) * 3
                         + ((gj_c < WWID - WS) ? 0 : ((gj_c < WWID - SHIFTV) ? 1 : 2));
                float v = s[mi][n2][e] * SCALE + b + ((clsJ != clsI) ? -100.f : 0.f);
                s[mi][n2][e] = v;
            }
        }
        // row max (rows r0 and r0+8)
        float mx0 = -1e30f, mx1 = -1e30f;
#pragma unroll
        for (int n2 = 0; n2 < 8; n2++) {
            mx0 = fmaxf(mx0, fmaxf(s[mi][n2][0], s[mi][n2][1]));
            mx1 = fmaxf(mx1, fmaxf(s[mi][n2][2], s[mi][n2][3]));
        }
        mx0 = fmaxf(mx0, __shfl_xor_sync(0xffffffffu, mx0, 1));
        mx0 = fmaxf(mx0, __shfl_xor_sync(0xffffffffu, mx0, 2));
        mx1 = fmaxf(mx1, __shfl_xor_sync(0xffffffffu, mx1, 1));
        mx1 = fmaxf(mx1, __shfl_xor_sync(0xffffffffu, mx1, 2));
        float sum0 = 0.f, sum1 = 0.f;
#pragma unroll
        for (int n2 = 0; n2 < 8; n2++) {
            s[mi][n2][0] = __expf(s[mi][n2][0] - mx0);
            s[mi][n2][1] = __expf(s[mi][n2][1] - mx0);
            s[mi][n2][2] = __expf(s[mi][n2][2] - mx1);
            s[mi][n2][3] = __expf(s[mi][n2][3] - mx1);
            sum0 += s[mi][n2][0] + s[mi][n2][1];
            sum1 += s[mi][n2][2] + s[mi][n2][3];
        }
        sum0 += __shfl_xor_sync(0xffffffffu, sum0, 1);
        sum0 += __shfl_xor_sync(0xffffffffu, sum0, 2);
        sum1 += __shfl_xor_sync(0xffffffffu, sum1, 1);
        sum1 += __shfl_xor_sync(0xffffffffu, sum1, 2);
        float inv0 = 1.f / sum0, inv1 = 1.f / sum1;
#pragma unroll
        for (int n2 = 0; n2 < 8; n2++) {
            s[mi][n2][0] *= inv0; s[mi][n2][1] *= inv0;
            s[mi][n2][2] *= inv1; s[mi][n2][3] *= inv1;
        }
    }

    // ---- O = P @ V ----
    float o[2][4][4];
#pragma unroll
    for (int mi = 0; mi < 2; mi++)
#pragma unroll
        for (int d2 = 0; d2 < 4; d2++)
#pragma unroll
            for (int e = 0; e < 4; e++) o[mi][d2][e] = 0.f;

#pragma unroll
    for (int kp = 0; kp < 4; kp++) {
        uint32_t pf[2][4];
#pragma unroll
        for (int mi = 0; mi < 2; mi++) {
            pf[mi][0] = packbf2(s[mi][2 * kp + 0][0], s[mi][2 * kp + 0][1]);
            pf[mi][1] = packbf2(s[mi][2 * kp + 0][2], s[mi][2 * kp + 0][3]);
            pf[mi][2] = packbf2(s[mi][2 * kp + 1][0], s[mi][2 * kp + 1][1]);
            pf[mi][3] = packbf2(s[mi][2 * kp + 1][2], s[mi][2 * kp + 1][3]);
        }
#pragma unroll
        for (int dh = 0; dh < 2; dh++) {
            uint32_t vf[4];
            int vrow = 16 * kp + (lane & 7) + 8 * ((lane >> 3) & 1);
            uint32_t vcol = (uint32_t)(dh * 32 + ((lane >> 4) << 4));
            ldm4t(vf, Vb + (uint32_t)vrow * 80 + vcol);
#pragma unroll
            for (int mi = 0; mi < 2; mi++) {
                mma_bf16(o[mi][2 * dh + 0], pf[mi], vf[0], vf[1]);
                mma_bf16(o[mi][2 * dh + 1], pf[mi], vf[2], vf[3]);
            }
        }
    }

    // ---- store ----
#pragma unroll
    for (int mi = 0; mi < 2; mi++) {
        int r0 = half * 32 + 16 * mi + g;
        size_t ob0 = ((size_t)w * NN + r0) * CC + h * HD;
        size_t ob1 = ((size_t)w * NN + r0 + 8) * CC + h * HD;
#pragma unroll
        for (int d2 = 0; d2 < 4; d2++) {
            int c = 8 * d2 + 2 * t4;
            *(uint32_t*)(outp + ob0 + c) = packbf2(o[mi][d2][0], o[mi][d2][1]);
            *(uint32_t*)(outp + ob1 + c) = packbf2(o[mi][d2][2], o[mi][d2][3]);
        }
    }
}

// ================= host =================
extern "C" void kernel_launch(void* const* d_in, const int* in_sizes, int n_in,
                              void* d_out, int out_size) {
    const float* x     = (const float*)d_in[0];
    const float* n1g   = (const float*)d_in[1];
    const float* n1b   = (const float*)d_in[2];
    const float* qkvw  = (const float*)d_in[3];
    const float* qkvb  = (const float*)d_in[4];
    const float* projw = (const float*)d_in[5];
    const float* projb = (const float*)d_in[6];
    const float* rpb   = (const float*)d_in[7];
    const float* n2g   = (const float*)d_in[8];
    const float* n2b   = (const float*)d_in[9];
    const float* fc1w  = (const float*)d_in[10];
    const float* fc1b  = (const float*)d_in[11];
    const float* fc2w  = (const float*)d_in[12];
    const float* fc2b  = (const float*)d_in[13];
    float* out = (float*)d_out;

    __nv_bfloat16 *xw, *qkv, *attn, *m1, *wb;
    float *h;
    cudaGetSymbolAddress((void**)&xw,   g_xw);
    cudaGetSymbolAddress((void**)&qkv,  g_qkv);
    cudaGetSymbolAddress((void**)&attn, g_attn);
    cudaGetSymbolAddress((void**)&h,    g_h);
    cudaGetSymbolAddress((void**)&m1,   g_m1);
    cudaGetSymbolAddress((void**)&wb,   g_wb);

    cudaFuncSetAttribute(bgemm<0>, cudaFuncAttributeMaxDynamicSharedMemorySize, GSMEM);
    cudaFuncSetAttribute(bgemm<1>, cudaFuncAttributeMaxDynamicSharedMemorySize, GSMEM);
    cudaFuncSetAttribute(bgemm<2>, cudaFuncAttributeMaxDynamicSharedMemorySize, GSMEM);
    cudaFuncSetAttribute(bgemm<3>, cudaFuncAttributeMaxDynamicSharedMemorySize, GSMEM);
    cudaFuncSetAttribute(attn_mma, cudaFuncAttributeMaxDynamicSharedMemorySize, AT_SMEM);

    // 0. weight conversion (tiny)
    wconv<<<(C3 * CC / 4 + 255) / 256, 256>>>(qkvw, wb + WB_QKV, C3 * CC);
    wconv<<<(CC * CC / 4 + 255) / 256, 256>>>(projw, wb + WB_PROJ, CC * CC);
    wconv<<<(C4 * CC / 4 + 255) / 256, 256>>>(fc1w, wb + WB_FC1, C4 * CC);
    wconv<<<(CC * C4 / 4 + 255) / 256, 256>>>(fc2w, wb + WB_FC2, CC * C4);

    // 1. LN1 + shift + window partition
    ln_kernel<1><<<TT / 8, 256>>>(x, n1g, n1b, xw);
    // 2. QKV
    bgemm<0><<<dim3(C3 / BN, TT / BM), 256, GSMEM>>>(xw, wb + WB_QKV, qkvb, qkv, nullptr, C3, CC);
    // 3. Attention (tensor cores)
    attn_mma<<<BWIN, AT_THREADS, AT_SMEM>>>(qkv, rpb, attn);
    // 4. Proj + window reverse + unshift + residual(x) -> h fp32
    bgemm<1><<<dim3(CC / BN, TT / BM), 256, GSMEM>>>(attn, wb + WB_PROJ, projb, h, x, CC, CC);
    // 5. LN2
    ln_kernel<0><<<TT / 8, 256>>>(h, n2g, n2b, xw);
    // 6. FC1 + GELU
    bgemm<2><<<dim3(C4 / BN, TT / BM), 256, GSMEM>>>(xw, wb + WB_FC1, fc1b, m1, nullptr, C4, CC);
    // 7. FC2 + residual(h) -> out fp32
    bgemm<3><<<dim3(CC / BN, TT / BM), 256, GSMEM>>>(m1, wb + WB_FC2, fc2b, out, h, CC, C4);
}